// round 5
// baseline (speedup 1.0000x reference)
#include <cuda_runtime.h>
#include <math.h>

#define NNODES 500000
#define NEDGES 8000000
#define FIN 16
#define HID 8
#define NCLS 2
#define SCAN_B 1024
#define NB ((NNODES + SCAN_B - 1) / SCAN_B)   // 489

// ---------------- device scratch ----------------
__device__ int   g_cnt   [NNODES];
__device__ int   g_starts[NNODES + 1];
__device__ int   g_cursor[NNODES];
__device__ int   g_bsum  [NB];
__device__ int   g_eids  [NEDGES];
__device__ float g_dinv  [NNODES];
__device__ float g_p1    [NNODES * HID];
__device__ float g_p2d   [NNODES];

// ---------------------------------------------------------------------------
// K0: zero counters
// ---------------------------------------------------------------------------
__global__ void k_zero(int n) {
    int i = blockIdx.x * blockDim.x + threadIdx.x;
    if (i < n) g_cnt[i] = 0;
}

// ---------------------------------------------------------------------------
// K1: in-degree count (int atomics), vectorized edge reads
// ---------------------------------------------------------------------------
__global__ void k_count(const int* __restrict__ col, int e4) {
    int t = blockIdx.x * blockDim.x + threadIdx.x;
    if (t >= e4) return;
    int4 c = ((const int4*)col)[t];
    atomicAdd(&g_cnt[c.x], 1);
    atomicAdd(&g_cnt[c.y], 1);
    atomicAdd(&g_cnt[c.z], 1);
    atomicAdd(&g_cnt[c.w], 1);
}

// ---------------------------------------------------------------------------
// K2a: per-block sums of cnt
// ---------------------------------------------------------------------------
__global__ void k_scan_blk(int n) {
    __shared__ int s[SCAN_B];
    int i = blockIdx.x * SCAN_B + threadIdx.x;
    s[threadIdx.x] = (i < n) ? g_cnt[i] : 0;
    __syncthreads();
    for (int off = SCAN_B / 2; off > 0; off >>= 1) {
        if (threadIdx.x < off) s[threadIdx.x] += s[threadIdx.x + off];
        __syncthreads();
    }
    if (threadIdx.x == 0) g_bsum[blockIdx.x] = s[0];
}

// ---------------------------------------------------------------------------
// K2b: single-block exclusive scan of block sums; also writes starts[n]=E
// ---------------------------------------------------------------------------
__global__ void k_scan_top(int nb, int n, int e) {
    __shared__ int s[512];
    int tid = threadIdx.x;
    int v = (tid < nb) ? g_bsum[tid] : 0;
    s[tid] = v;
    __syncthreads();
    for (int off = 1; off < 512; off <<= 1) {
        int t = (tid >= off) ? s[tid - off] : 0;
        __syncthreads();
        s[tid] += t;
        __syncthreads();
    }
    if (tid < nb) g_bsum[tid] = s[tid] - v;   // exclusive
    if (tid == 0) g_starts[n] = e;
}

// ---------------------------------------------------------------------------
// K2c: per-block exclusive scan + block offset -> starts, cursor, dinv
// ---------------------------------------------------------------------------
__global__ void k_scan_fin(int n) {
    __shared__ int s[SCAN_B];
    int tid = threadIdx.x;
    int i = blockIdx.x * SCAN_B + tid;
    int v = (i < n) ? g_cnt[i] : 0;
    s[tid] = v;
    __syncthreads();
    for (int off = 1; off < SCAN_B; off <<= 1) {
        int t = (tid >= off) ? s[tid - off] : 0;
        __syncthreads();
        s[tid] += t;
        __syncthreads();
    }
    if (i < n) {
        int st = g_bsum[blockIdx.x] + s[tid] - v;   // exclusive scan value
        g_starts[i] = st;
        g_cursor[i] = st;
        g_dinv[i]   = rsqrtf((float)(v + 1));       // +1 self-loop
    }
}

// ---------------------------------------------------------------------------
// K3: CSR fill — eids[pos] = row, pos via cursor atomics
// ---------------------------------------------------------------------------
__global__ void k_fill(const int* __restrict__ row,
                       const int* __restrict__ col, int e4) {
    int t = blockIdx.x * blockDim.x + threadIdx.x;
    if (t >= e4) return;
    int4 r = ((const int4*)row)[t];
    int4 c = ((const int4*)col)[t];
    g_eids[atomicAdd(&g_cursor[c.x], 1)] = r.x;
    g_eids[atomicAdd(&g_cursor[c.y], 1)] = r.y;
    g_eids[atomicAdd(&g_cursor[c.z], 1)] = r.z;
    g_eids[atomicAdd(&g_cursor[c.w], 1)] = r.w;
}

// ---------------------------------------------------------------------------
// K4: per-node p1 = (x @ W1) * dinv
// ---------------------------------------------------------------------------
__global__ void k_p1(const float* __restrict__ x,
                     const float* __restrict__ W1, int n) {
    __shared__ float sW1[FIN * HID];
    for (int k = threadIdx.x; k < FIN * HID; k += blockDim.x) sW1[k] = W1[k];
    __syncthreads();

    int i = blockIdx.x * blockDim.x + threadIdx.x;
    if (i >= n) return;

    const float4* xr = (const float4*)(x + (size_t)i * FIN);
    float xv[FIN];
    #pragma unroll
    for (int q = 0; q < 4; q++) {
        float4 v = xr[q];
        xv[q*4+0] = v.x; xv[q*4+1] = v.y; xv[q*4+2] = v.z; xv[q*4+3] = v.w;
    }
    float h[HID];
    #pragma unroll
    for (int j = 0; j < HID; j++) h[j] = 0.f;
    #pragma unroll
    for (int k = 0; k < FIN; k++) {
        float xk = xv[k];
        #pragma unroll
        for (int j = 0; j < HID; j++) h[j] = fmaf(xk, sW1[k*HID + j], h[j]);
    }
    float d = g_dinv[i];
    ((float4*)(g_p1 + (size_t)i * HID))[0] = make_float4(h[0]*d, h[1]*d, h[2]*d, h[3]*d);
    ((float4*)(g_p1 + (size_t)i * HID))[1] = make_float4(h[4]*d, h[5]*d, h[6]*d, h[7]*d);
}

// ---------------------------------------------------------------------------
// K5: layer-1 aggregate (CSR gather, 8 lanes per node) fused with
//     relu + W2-delta projection -> p2d
// ---------------------------------------------------------------------------
__global__ void k_agg1(const float* __restrict__ b1,
                       const float* __restrict__ W2, int n) {
    int gt   = blockIdx.x * blockDim.x + threadIdx.x;
    int node = gt >> 3;
    int sub  = gt & 7;
    if (node >= n) return;

    int s = g_starts[node];
    int t = g_starts[node + 1];

    float a[HID];
    #pragma unroll
    for (int j = 0; j < HID; j++) a[j] = 0.f;

    for (int e = s + sub; e < t; e += 8) {
        int r = __ldg(&g_eids[e]);
        const float4* p = (const float4*)(g_p1 + (size_t)r * HID);
        float4 u = __ldg(p);
        float4 w = __ldg(p + 1);
        a[0] += u.x; a[1] += u.y; a[2] += u.z; a[3] += u.w;
        a[4] += w.x; a[5] += w.y; a[6] += w.z; a[7] += w.w;
    }
    // octet reduction
    #pragma unroll
    for (int off = 4; off > 0; off >>= 1) {
        #pragma unroll
        for (int j = 0; j < HID; j++)
            a[j] += __shfl_down_sync(0xFFFFFFFFu, a[j], off, 8);
    }

    if (sub == 0) {
        float d = g_dinv[node];
        const float4* ps = (const float4*)(g_p1 + (size_t)node * HID);
        float4 s0 = ps[0], s1 = ps[1];
        float self[HID] = {s0.x, s0.y, s0.z, s0.w, s1.x, s1.y, s1.z, s1.w};
        float zd = 0.f;
        #pragma unroll
        for (int j = 0; j < HID; j++) {
            float h = fmaxf(d * (a[j] + self[j]) + __ldg(b1 + j), 0.f);
            zd = fmaf(h, __ldg(W2 + j*NCLS + 1) - __ldg(W2 + j*NCLS + 0), zd);
        }
        g_p2d[node] = zd * d;
    }
}

// ---------------------------------------------------------------------------
// K6: layer-2 scalar aggregate (CSR gather, 8 lanes per node) fused with
//     bias + 2-class log_softmax output
// ---------------------------------------------------------------------------
__global__ void k_agg2(const float* __restrict__ b2,
                       float* __restrict__ out, int n) {
    int gt   = blockIdx.x * blockDim.x + threadIdx.x;
    int node = gt >> 3;
    int sub  = gt & 7;
    if (node >= n) return;

    int s = g_starts[node];
    int t = g_starts[node + 1];

    float a = 0.f;
    for (int e = s + sub; e < t; e += 8)
        a += __ldg(&g_p2d[__ldg(&g_eids[e])]);

    #pragma unroll
    for (int off = 4; off > 0; off >>= 1)
        a += __shfl_down_sync(0xFFFFFFFFu, a, off, 8);

    if (sub == 0) {
        float d     = g_dinv[node];
        float bd    = __ldg(b2 + 1) - __ldg(b2 + 0);
        float delta = d * (a + g_p2d[node]) + bd;          // o1 - o0
        float sp    = fmaxf(delta, 0.f) + log1pf(expf(-fabsf(delta)));
        ((float2*)out)[node] = make_float2(-sp, delta - sp);
    }
}

// ---------------------------------------------------------------------------
extern "C" void kernel_launch(void* const* d_in, const int* in_sizes, int n_in,
                              void* d_out, int out_size) {
    const float* x  = (const float*)d_in[0];
    const float* W1 = (const float*)d_in[1];
    const float* b1 = (const float*)d_in[2];
    const float* W2 = (const float*)d_in[3];
    const float* b2 = (const float*)d_in[4];
    const int*   ei = (const int*)  d_in[5];

    int n = in_sizes[0] / FIN;         // 500000
    int e = in_sizes[5] / 2;           // 8000000
    const int* row = ei;
    const int* col = ei + e;
    float* out = (float*)d_out;

    const int TB = 256;
    int gn  = (n + TB - 1) / TB;
    int e4  = e / 4;                   // E divisible by 4
    int ge4 = (e4 + TB - 1) / TB;
    int nb  = (n + SCAN_B - 1) / SCAN_B;
    int g8  = (n * 8 + TB - 1) / TB;   // octet kernels

    k_zero    <<<gn, TB>>>(n);
    k_count   <<<ge4, TB>>>(col, e4);
    k_scan_blk<<<nb, SCAN_B>>>(n);
    k_scan_top<<<1, 512>>>(nb, n, e);
    k_scan_fin<<<nb, SCAN_B>>>(n);
    k_fill    <<<ge4, TB>>>(row, col, e4);
    k_p1      <<<gn, TB>>>(x, W1, n);
    k_agg1    <<<g8, TB>>>(b1, W2, n);
    k_agg2    <<<g8, TB>>>(b2, out, n);
}

// round 6
// speedup vs baseline: 1.2340x; 1.2340x over previous
#include <cuda_runtime.h>
#include <cuda_fp16.h>
#include <math.h>

#define NNODES 500000
#define FIN 16
#define HID 8
#define NCLS 2

// ---------------- device scratch ----------------
__device__ float   g_deg  [NNODES];           // degree incl. self-loop
__device__ float   g_dinv [NNODES];           // deg^{-1/2}
__device__ float   g_p1   [NNODES * HID];     // (x@W1)*dinv, f32 (self-loop path)
__device__ __half2 g_p1h  [NNODES * 4];       // same, f16 (gather path)
__device__ float   g_agg1 [NNODES * HID];     // layer-1 scatter target
__device__ float   g_p2d  [NNODES];           // scalar delta message, layer 2
__device__ float   g_agg2 [NNODES];           // layer-2 scatter target (scalar)

// ---------------------------------------------------------------------------
__device__ __forceinline__ void red_add_v4(float* p, float4 v) {
    asm volatile("red.global.add.v4.f32 [%0], {%1,%2,%3,%4};"
                 :: "l"(p), "f"(v.x), "f"(v.y), "f"(v.z), "f"(v.w) : "memory");
}
__device__ __forceinline__ void red_add_f(float* p, float v) {
    asm volatile("red.global.add.f32 [%0], %1;" :: "l"(p), "f"(v) : "memory");
}

// ---------------------------------------------------------------------------
// K0: init — deg=1 (self loop), zero scatter targets
// ---------------------------------------------------------------------------
__global__ void k_init(int n) {
    int i = blockIdx.x * blockDim.x + threadIdx.x;
    if (i >= n) return;
    g_deg[i]  = 1.0f;
    g_agg2[i] = 0.0f;
    float4 z = make_float4(0.f, 0.f, 0.f, 0.f);
    ((float4*)(g_agg1 + (size_t)i * HID))[0] = z;
    ((float4*)(g_agg1 + (size_t)i * HID))[1] = z;
}

// ---------------------------------------------------------------------------
// K1: degree — deg[col] += 1, 4 edges/thread
// ---------------------------------------------------------------------------
__global__ void k_degree(const int* __restrict__ col, int e4) {
    int t = blockIdx.x * blockDim.x + threadIdx.x;
    if (t >= e4) return;
    int4 c = ((const int4*)col)[t];
    red_add_f(&g_deg[c.x], 1.0f);
    red_add_f(&g_deg[c.y], 1.0f);
    red_add_f(&g_deg[c.z], 1.0f);
    red_add_f(&g_deg[c.w], 1.0f);
}

// ---------------------------------------------------------------------------
// K2: per-node — dinv = rsqrt(deg); p1 = (x@W1)*dinv in f32 and f16
// ---------------------------------------------------------------------------
__global__ void k_p1(const float* __restrict__ x,
                     const float* __restrict__ W1, int n) {
    __shared__ float sW1[FIN * HID];
    for (int k = threadIdx.x; k < FIN * HID; k += blockDim.x) sW1[k] = W1[k];
    __syncthreads();

    int i = blockIdx.x * blockDim.x + threadIdx.x;
    if (i >= n) return;

    const float4* xr = (const float4*)(x + (size_t)i * FIN);
    float xv[FIN];
    #pragma unroll
    for (int q = 0; q < 4; q++) {
        float4 v = xr[q];
        xv[q*4+0] = v.x; xv[q*4+1] = v.y; xv[q*4+2] = v.z; xv[q*4+3] = v.w;
    }
    float h[HID];
    #pragma unroll
    for (int j = 0; j < HID; j++) h[j] = 0.f;
    #pragma unroll
    for (int k = 0; k < FIN; k++) {
        float xk = xv[k];
        #pragma unroll
        for (int j = 0; j < HID; j++) h[j] = fmaf(xk, sW1[k*HID + j], h[j]);
    }
    float d = rsqrtf(g_deg[i]);
    g_dinv[i] = d;
    #pragma unroll
    for (int j = 0; j < HID; j++) h[j] *= d;

    ((float4*)(g_p1 + (size_t)i * HID))[0] = make_float4(h[0], h[1], h[2], h[3]);
    ((float4*)(g_p1 + (size_t)i * HID))[1] = make_float4(h[4], h[5], h[6], h[7]);

    __half2 hh[4];
    #pragma unroll
    for (int q = 0; q < 4; q++)
        hh[q] = __floats2half2_rn(h[2*q], h[2*q+1]);
    ((uint4*)(g_p1h + (size_t)i * 4))[0] = *(uint4*)hh;
}

// ---------------------------------------------------------------------------
// K3: edge scatter, layer 1 — f16 gather (16B), f32 v4 REDs; 2 edges/thread
// ---------------------------------------------------------------------------
__global__ void k_scatter1(const int* __restrict__ row,
                           const int* __restrict__ col, int e2) {
    int t = blockIdx.x * blockDim.x + threadIdx.x;
    if (t >= e2) return;
    int2 r2 = ((const int2*)row)[t];
    int2 c2 = ((const int2*)col)[t];

    uint4 m0 = __ldg((const uint4*)(g_p1h + (size_t)r2.x * 4));
    uint4 m1 = __ldg((const uint4*)(g_p1h + (size_t)r2.y * 4));

    {
        __half2* hp = (__half2*)&m0;
        float2 f0 = __half22float2(hp[0]);
        float2 f1 = __half22float2(hp[1]);
        float2 f2 = __half22float2(hp[2]);
        float2 f3 = __half22float2(hp[3]);
        float* dst = g_agg1 + (size_t)c2.x * HID;
        red_add_v4(dst,     make_float4(f0.x, f0.y, f1.x, f1.y));
        red_add_v4(dst + 4, make_float4(f2.x, f2.y, f3.x, f3.y));
    }
    {
        __half2* hp = (__half2*)&m1;
        float2 f0 = __half22float2(hp[0]);
        float2 f1 = __half22float2(hp[1]);
        float2 f2 = __half22float2(hp[2]);
        float2 f3 = __half22float2(hp[3]);
        float* dst = g_agg1 + (size_t)c2.y * HID;
        red_add_v4(dst,     make_float4(f0.x, f0.y, f1.x, f1.y));
        red_add_v4(dst + 4, make_float4(f2.x, f2.y, f3.x, f3.y));
    }
}

// ---------------------------------------------------------------------------
// K4: per-node — h = relu(d*(agg1+p1)+b1); p2d = (h @ (W2c1-W2c0)) * d
// ---------------------------------------------------------------------------
__global__ void k_layer1(const float* __restrict__ b1,
                         const float* __restrict__ W2, int n) {
    __shared__ float sWd[HID];
    __shared__ float sb1[HID];
    if (threadIdx.x < HID) {
        sWd[threadIdx.x] = W2[threadIdx.x * NCLS + 1] - W2[threadIdx.x * NCLS + 0];
        sb1[threadIdx.x] = b1[threadIdx.x];
    }
    __syncthreads();

    int i = blockIdx.x * blockDim.x + threadIdx.x;
    if (i >= n) return;

    float d = g_dinv[i];
    const float4* ag = (const float4*)(g_agg1 + (size_t)i * HID);
    const float4* pp = (const float4*)(g_p1  + (size_t)i * HID);
    float4 a0 = ag[0], a1 = ag[1];
    float4 p0 = pp[0], p1v = pp[1];
    float h[HID] = {
        d*(a0.x + p0.x),  d*(a0.y + p0.y),  d*(a0.z + p0.z),  d*(a0.w + p0.w),
        d*(a1.x + p1v.x), d*(a1.y + p1v.y), d*(a1.z + p1v.z), d*(a1.w + p1v.w)};
    float zd = 0.f;
    #pragma unroll
    for (int j = 0; j < HID; j++) {
        float hv = fmaxf(h[j] + sb1[j], 0.f);
        zd = fmaf(hv, sWd[j], zd);
    }
    g_p2d[i] = zd * d;
}

// ---------------------------------------------------------------------------
// K5: edge scatter, layer 2 — scalar gather + scalar RED; 4 edges/thread
// ---------------------------------------------------------------------------
__global__ void k_scatter2(const int* __restrict__ row,
                           const int* __restrict__ col, int e4) {
    int t = blockIdx.x * blockDim.x + threadIdx.x;
    if (t >= e4) return;
    int4 r = ((const int4*)row)[t];
    int4 c = ((const int4*)col)[t];
    float v0 = __ldg(&g_p2d[r.x]);
    float v1 = __ldg(&g_p2d[r.y]);
    float v2 = __ldg(&g_p2d[r.z]);
    float v3 = __ldg(&g_p2d[r.w]);
    red_add_f(&g_agg2[c.x], v0);
    red_add_f(&g_agg2[c.y], v1);
    red_add_f(&g_agg2[c.z], v2);
    red_add_f(&g_agg2[c.w], v3);
}

// ---------------------------------------------------------------------------
// K6: per-node — delta = d*(agg2+p2d)+(b2[1]-b2[0]); stable 2-class log_softmax
// ---------------------------------------------------------------------------
__global__ void k_out(const float* __restrict__ b2, float* __restrict__ out, int n) {
    int i = blockIdx.x * blockDim.x + threadIdx.x;
    if (i >= n) return;
    float d  = g_dinv[i];
    float bd = __ldg(b2 + 1) - __ldg(b2 + 0);
    float delta = d * (g_agg2[i] + g_p2d[i]) + bd;          // o1 - o0
    float sp = fmaxf(delta, 0.f) + log1pf(expf(-fabsf(delta)));
    ((float2*)out)[i] = make_float2(-sp, delta - sp);
}

// ---------------------------------------------------------------------------
extern "C" void kernel_launch(void* const* d_in, const int* in_sizes, int n_in,
                              void* d_out, int out_size) {
    const float* x  = (const float*)d_in[0];
    const float* W1 = (const float*)d_in[1];
    const float* b1 = (const float*)d_in[2];
    const float* W2 = (const float*)d_in[3];
    const float* b2 = (const float*)d_in[4];
    const int*   ei = (const int*)  d_in[5];

    int n = in_sizes[0] / FIN;         // 500000
    int e = in_sizes[5] / 2;           // 8000000
    const int* row = ei;
    const int* col = ei + e;
    float* out = (float*)d_out;

    const int TB = 256;
    int gn  = (n + TB - 1) / TB;
    int e2  = e / 2;
    int e4  = e / 4;
    int ge2 = (e2 + TB - 1) / TB;
    int ge4 = (e4 + TB - 1) / TB;

    k_init    <<<gn, TB>>>(n);
    k_degree  <<<ge4, TB>>>(col, e4);
    k_p1      <<<gn, TB>>>(x, W1, n);
    k_scatter1<<<ge2, TB>>>(row, col, e2);
    k_layer1  <<<gn, TB>>>(b1, W2, n);
    k_scatter2<<<ge4, TB>>>(row, col, e4);
    k_out     <<<gn, TB>>>(b2, out, n);
}

// round 8
// speedup vs baseline: 1.4899x; 1.2074x over previous
#include <cuda_runtime.h>
#include <cuda_fp16.h>
#include <math.h>

#define NNODES 500000
#define FIN 16
#define HID 8
#define NCLS 2

// ---------------- device scratch ----------------
__device__ float   g_deg  [NNODES];           // degree incl. self-loop
__device__ float   g_dinv [NNODES];           // deg^{-1/2}
__device__ __half2 g_p1h  [NNODES * 4];       // (x@W1)*dinv, f16 (messages + self)
__device__ __half2 g_agg1h[NNODES * 4];       // layer-1 accumulator, f16
__device__ float   g_p2d  [NNODES];           // scalar delta message, layer 2
__device__ float   g_agg2 [NNODES];           // layer-2 accumulator (f32 scalar)

// ---------------------------------------------------------------------------
__device__ __forceinline__ void red_add_v4h2(void* p, uint4 v) {
    asm volatile("red.global.add.noftz.v4.f16x2 [%0], {%1,%2,%3,%4};"
                 :: "l"(p), "r"(v.x), "r"(v.y), "r"(v.z), "r"(v.w) : "memory");
}
__device__ __forceinline__ void red_add_f(float* p, float v) {
    asm volatile("red.global.add.f32 [%0], %1;" :: "l"(p), "f"(v) : "memory");
}

// ---------------------------------------------------------------------------
// K0: init — deg=1 (self loop), zero both accumulators
// ---------------------------------------------------------------------------
__global__ void k_init(int n) {
    int i = blockIdx.x * blockDim.x + threadIdx.x;
    if (i >= n) return;
    g_deg[i]  = 1.0f;
    g_agg2[i] = 0.0f;
    ((uint4*)(g_agg1h + (size_t)i * 4))[0] = make_uint4(0u, 0u, 0u, 0u);
}

// ---------------------------------------------------------------------------
// K1: degree — deg[col] += 1, 4 edges/thread
// ---------------------------------------------------------------------------
__global__ void k_degree(const int* __restrict__ col, int e4) {
    int t = blockIdx.x * blockDim.x + threadIdx.x;
    if (t >= e4) return;
    int4 c = ((const int4*)col)[t];
    red_add_f(&g_deg[c.x], 1.0f);
    red_add_f(&g_deg[c.y], 1.0f);
    red_add_f(&g_deg[c.z], 1.0f);
    red_add_f(&g_deg[c.w], 1.0f);
}

// ---------------------------------------------------------------------------
// K2: per-node — dinv = rsqrt(deg); p1h = f16((x@W1)*dinv)
// ---------------------------------------------------------------------------
__global__ void k_p1(const float* __restrict__ x,
                     const float* __restrict__ W1, int n) {
    __shared__ float sW1[FIN * HID];
    for (int k = threadIdx.x; k < FIN * HID; k += blockDim.x) sW1[k] = W1[k];
    __syncthreads();

    int i = blockIdx.x * blockDim.x + threadIdx.x;
    if (i >= n) return;

    const float4* xr = (const float4*)(x + (size_t)i * FIN);
    float xv[FIN];
    #pragma unroll
    for (int q = 0; q < 4; q++) {
        float4 v = xr[q];
        xv[q*4+0] = v.x; xv[q*4+1] = v.y; xv[q*4+2] = v.z; xv[q*4+3] = v.w;
    }
    float h[HID];
    #pragma unroll
    for (int j = 0; j < HID; j++) h[j] = 0.f;
    #pragma unroll
    for (int k = 0; k < FIN; k++) {
        float xk = xv[k];
        #pragma unroll
        for (int j = 0; j < HID; j++) h[j] = fmaf(xk, sW1[k*HID + j], h[j]);
    }
    float d = rsqrtf(g_deg[i]);
    g_dinv[i] = d;

    __half2 hh[4];
    #pragma unroll
    for (int q = 0; q < 4; q++)
        hh[q] = __floats2half2_rn(h[2*q] * d, h[2*q+1] * d);
    ((uint4*)(g_p1h + (size_t)i * 4))[0] = *(uint4*)hh;
}

// ---------------------------------------------------------------------------
// K3: edge scatter, layer 1 — 16B f16 gather + ONE v4.f16x2 RED; 2 edges/thread
// ---------------------------------------------------------------------------
__global__ void k_scatter1(const int* __restrict__ row,
                           const int* __restrict__ col, int e2) {
    int t = blockIdx.x * blockDim.x + threadIdx.x;
    if (t >= e2) return;
    int2 r2 = ((const int2*)row)[t];
    int2 c2 = ((const int2*)col)[t];

    uint4 m0 = __ldg((const uint4*)(g_p1h + (size_t)r2.x * 4));
    uint4 m1 = __ldg((const uint4*)(g_p1h + (size_t)r2.y * 4));

    red_add_v4h2(g_agg1h + (size_t)c2.x * 4, m0);
    red_add_v4h2(g_agg1h + (size_t)c2.y * 4, m1);
}

// ---------------------------------------------------------------------------
// K4: per-node — h = relu(d*(agg1+p1)+b1); p2d = (h @ (W2c1-W2c0)) * d
// ---------------------------------------------------------------------------
__global__ void k_layer1(const float* __restrict__ b1,
                         const float* __restrict__ W2, int n) {
    __shared__ float sWd[HID];
    __shared__ float sb1[HID];
    if (threadIdx.x < HID) {
        sWd[threadIdx.x] = W2[threadIdx.x * NCLS + 1] - W2[threadIdx.x * NCLS + 0];
        sb1[threadIdx.x] = b1[threadIdx.x];
    }
    __syncthreads();

    int i = blockIdx.x * blockDim.x + threadIdx.x;
    if (i >= n) return;

    float d = g_dinv[i];
    uint4 au = ((const uint4*)(g_agg1h + (size_t)i * 4))[0];
    uint4 pu = ((const uint4*)(g_p1h   + (size_t)i * 4))[0];
    __half2* ah = (__half2*)&au;
    __half2* ph = (__half2*)&pu;

    float zd = 0.f;
    #pragma unroll
    for (int q = 0; q < 4; q++) {
        float2 a = __half22float2(ah[q]);
        float2 p = __half22float2(ph[q]);
        float h0 = fmaxf(d * (a.x + p.x) + sb1[2*q],   0.f);
        float h1 = fmaxf(d * (a.y + p.y) + sb1[2*q+1], 0.f);
        zd = fmaf(h0, sWd[2*q],   zd);
        zd = fmaf(h1, sWd[2*q+1], zd);
    }
    g_p2d[i] = zd * d;
}

// ---------------------------------------------------------------------------
// K5: edge scatter, layer 2 — scalar gather + scalar RED; 4 edges/thread
// ---------------------------------------------------------------------------
__global__ void k_scatter2(const int* __restrict__ row,
                           const int* __restrict__ col, int e4) {
    int t = blockIdx.x * blockDim.x + threadIdx.x;
    if (t >= e4) return;
    int4 r = ((const int4*)row)[t];
    int4 c = ((const int4*)col)[t];
    float v0 = __ldg(&g_p2d[r.x]);
    float v1 = __ldg(&g_p2d[r.y]);
    float v2 = __ldg(&g_p2d[r.z]);
    float v3 = __ldg(&g_p2d[r.w]);
    red_add_f(&g_agg2[c.x], v0);
    red_add_f(&g_agg2[c.y], v1);
    red_add_f(&g_agg2[c.z], v2);
    red_add_f(&g_agg2[c.w], v3);
}

// ---------------------------------------------------------------------------
// K6: per-node — delta = d*(agg2+p2d)+(b2[1]-b2[0]); stable 2-class log_softmax
// ---------------------------------------------------------------------------
__global__ void k_out(const float* __restrict__ b2, float* __restrict__ out, int n) {
    int i = blockIdx.x * blockDim.x + threadIdx.x;
    if (i >= n) return;
    float d  = g_dinv[i];
    float bd = __ldg(b2 + 1) - __ldg(b2 + 0);
    float delta = d * (g_agg2[i] + g_p2d[i]) + bd;          // o1 - o0
    float sp = fmaxf(delta, 0.f) + log1pf(expf(-fabsf(delta)));
    ((float2*)out)[i] = make_float2(-sp, delta - sp);
}

// ---------------------------------------------------------------------------
extern "C" void kernel_launch(void* const* d_in, const int* in_sizes, int n_in,
                              void* d_out, int out_size) {
    const float* x  = (const float*)d_in[0];
    const float* W1 = (const float*)d_in[1];
    const float* b1 = (const float*)d_in[2];
    const float* W2 = (const float*)d_in[3];
    const float* b2 = (const float*)d_in[4];
    const int*   ei = (const int*)  d_in[5];

    int n = in_sizes[0] / FIN;         // 500000
    int e = in_sizes[5] / 2;           // 8000000
    const int* row = ei;
    const int* col = ei + e;
    float* out = (float*)d_out;

    const int TB = 256;
    int gn  = (n + TB - 1) / TB;
    int e2  = e / 2;
    int e4  = e / 4;
    int ge2 = (e2 + TB - 1) / TB;
    int ge4 = (e4 + TB - 1) / TB;

    k_init    <<<gn, TB>>>(n);
    k_degree  <<<ge4, TB>>>(col, e4);
    k_p1      <<<gn, TB>>>(x, W1, n);
    k_scatter1<<<ge2, TB>>>(row, col, e2);
    k_layer1  <<<gn, TB>>>(b1, W2, n);
    k_scatter2<<<ge4, TB>>>(row, col, e4);
    k_out     <<<gn, TB>>>(b2, out, n);
}